// round 2
// baseline (speedup 1.0000x reference)
#include <cuda_runtime.h>
#include <cuda_bf16.h>

// ---------------------------------------------------------------------------
// Net_80796924772492: small permuted-group CNN, B=64.
// Pipeline: dw1(5x5,g=3) -> permgroup1(+relu+pool) -> dw2(5x5,g=51)
//        -> permgroup2(+relu+pool) -> 1x1 conv 515->100 (+relu, flatten)
//        -> fc1(2500->120,relu) -> fc2(120->84,relu) -> fc3(84->10)
// ---------------------------------------------------------------------------

#define BATCH 64

// ---- intermediate buffers (device globals: no allocation allowed) ----------
__device__ float g_buf1[BATCH * 18 * 28 * 28];   // dw1 out
__device__ float g_buf2[BATCH * 51 * 14 * 14];   // pc1+relu+pool out
__device__ float g_buf3[BATCH * 255 * 10 * 10];  // dw2 out
__device__ float g_buf4[BATCH * 515 * 5 * 5];    // pc2+relu+pool out
__device__ float g_buf5[BATCH * 2500];           // oo out (flattened)
__device__ float g_buf6[BATCH * 120];            // fc1 out

// per-group info: (j, rep = i*ncpf+j, base = k*ncpf, 0)
__device__ int4 g_g1info[51];
__device__ int4 g_g2info[515];

// ---------------------------------------------------------------------------
// Init: derive per-group (i,j,k) from build_perm's enumeration order.
// For filter index i: j==0 contributes (F-i) groups (k = i..F-1),
// then j = 1..ncpf-1 each contributes (F-1-i) groups (k = i+1..F-1).
// ---------------------------------------------------------------------------
__device__ __forceinline__ int4 group_info(int g, int F, int ncpf) {
    int rem = g;
    int i = 0;
    for (;;) {
        int cnt = (F - i) + (ncpf - 1) * (F - 1 - i);
        if (rem < cnt) break;
        rem -= cnt;
        i++;
    }
    int j, k;
    if (rem < F - i) {
        j = 0;
        k = i + rem;
    } else {
        rem -= (F - i);
        j = 1 + rem / (F - 1 - i);
        k = i + 1 + rem % (F - 1 - i);
    }
    int4 r;
    r.x = j;
    r.y = i * ncpf + j;  // replacement channel
    r.z = k * ncpf;      // base of donor block
    r.w = 0;
    return r;
}

__global__ void init_groupinfo_kernel() {
    int g = blockIdx.x * blockDim.x + threadIdx.x;
    if (g < 51) {
        g_g1info[g] = group_info(g, 6, 3);
    } else if (g < 51 + 515) {
        g_g2info[g - 51] = group_info(g - 51, 5, 51);
    }
}

// ---------------------------------------------------------------------------
// dw1: x[64,3,32,32] -> [64,18,28,28], 5x5 depthwise-grouped (g=3, 6 out/grp)
// ---------------------------------------------------------------------------
__global__ void dw1_kernel(const float* __restrict__ x,
                           const float* __restrict__ w,
                           const float* __restrict__ bias) {
    int idx = blockIdx.x * blockDim.x + threadIdx.x;
    if (idx >= BATCH * 18 * 28 * 28) return;
    int xo = idx % 28;
    int t = idx / 28;
    int yo = t % 28; t /= 28;
    int o = t % 18;
    int b = t / 18;
    int ci = o / 6;
    const float* xp = x + (((b * 3 + ci) * 32 + yo) * 32 + xo);
    const float* wp = w + o * 25;
    float acc = bias[o];
#pragma unroll
    for (int ky = 0; ky < 5; ky++)
#pragma unroll
        for (int kx = 0; kx < 5; kx++)
            acc = fmaf(xp[ky * 32 + kx], __ldg(wp + ky * 5 + kx), acc);
    g_buf1[idx] = acc;
}

// ---------------------------------------------------------------------------
// pc1 (grouped 1x1 over 3 permuted channels) + relu + 2x2 maxpool
// in: g_buf1 [64,18,28,28]  out: g_buf2 [64,51,14,14]
// ---------------------------------------------------------------------------
__global__ void pc1pool_kernel(const float* __restrict__ w,
                               const float* __restrict__ bias) {
    int idx = blockIdx.x * blockDim.x + threadIdx.x;
    if (idx >= BATCH * 51 * 14 * 14) return;
    int px = idx % 14;
    int t = idx / 14;
    int py = t % 14; t /= 14;
    int g = t % 51;
    int b = t / 51;

    int4 gi = g_g1info[g];
    int ch0 = (gi.x == 0) ? gi.y : gi.z + 0;
    int ch1 = (gi.x == 1) ? gi.y : gi.z + 1;
    int ch2 = (gi.x == 2) ? gi.y : gi.z + 2;

    const float* base = g_buf1 + b * 18 * 784;
    const float* p0 = base + ch0 * 784;
    const float* p1 = base + ch1 * 784;
    const float* p2 = base + ch2 * 784;

    float w0 = __ldg(w + g * 3 + 0);
    float w1 = __ldg(w + g * 3 + 1);
    float w2 = __ldg(w + g * 3 + 2);
    float bb = __ldg(bias + g);

    float m = 0.0f;  // max of relus == max(0, raw values)
#pragma unroll
    for (int dy = 0; dy < 2; dy++) {
#pragma unroll
        for (int dx = 0; dx < 2; dx++) {
            int off = (2 * py + dy) * 28 + (2 * px + dx);
            float v = bb;
            v = fmaf(w0, p0[off], v);
            v = fmaf(w1, p1[off], v);
            v = fmaf(w2, p2[off], v);
            m = fmaxf(m, v);
        }
    }
    g_buf2[idx] = m;
}

// ---------------------------------------------------------------------------
// dw2: [64,51,14,14] -> [64,255,10,10], 5x5 grouped (g=51, 5 out/grp)
// ---------------------------------------------------------------------------
__global__ void dw2_kernel(const float* __restrict__ w,
                           const float* __restrict__ bias) {
    int idx = blockIdx.x * blockDim.x + threadIdx.x;
    if (idx >= BATCH * 255 * 100) return;
    int xo = idx % 10;
    int t = idx / 10;
    int yo = t % 10; t /= 10;
    int o = t % 255;
    int b = t / 255;
    int ci = o / 5;
    const float* xp = g_buf2 + ((b * 51 + ci) * 196 + yo * 14 + xo);
    const float* wp = w + o * 25;
    float acc = bias[o];
#pragma unroll
    for (int ky = 0; ky < 5; ky++)
#pragma unroll
        for (int kx = 0; kx < 5; kx++)
            acc = fmaf(xp[ky * 14 + kx], __ldg(wp + ky * 5 + kx), acc);
    g_buf3[idx] = acc;
}

// ---------------------------------------------------------------------------
// pc2 (grouped 1x1 over 51 permuted channels) + relu + 2x2 maxpool
// in: g_buf3 [64,255,10,10]  out: g_buf4 [64,515,5,5]
// block = (b, pooled row py); smem holds 255 channels x 2 rows x 10 cols.
// ---------------------------------------------------------------------------
__global__ void pc2pool_kernel(const float* __restrict__ w,
                               const float* __restrict__ bias) {
    __shared__ float s[255 * 20];  // 20.4 KB
    int b = blockIdx.x / 5;
    int py = blockIdx.x % 5;

    const float* src = g_buf3 + b * 25500 + (2 * py) * 10;  // chan stride 100
    for (int i = threadIdx.x; i < 255 * 20; i += blockDim.x) {
        int ch = i / 20;
        int off = i % 20;                 // r*10 + c
        s[i] = src[ch * 100 + (off / 10) * 10 + (off % 10)];
    }
    __syncthreads();

    for (int o = threadIdx.x; o < 515 * 5; o += blockDim.x) {
        int g = o / 5;
        int px = o % 5;
        int4 gi = g_g2info[g];
        int j = gi.x, rep = gi.y, base = gi.z;
        const float* wr = w + g * 51;
        float bb = __ldg(bias + g);
        float v00 = bb, v01 = bb, v10 = bb, v11 = bb;
        int c2 = 2 * px;
#pragma unroll 3
        for (int c = 0; c < 51; c++) {
            int ch = (c == j) ? rep : base + c;
            float ww = __ldg(wr + c);
            const float* sp = s + ch * 20 + c2;
            v00 = fmaf(ww, sp[0], v00);
            v01 = fmaf(ww, sp[1], v01);
            v10 = fmaf(ww, sp[10], v10);
            v11 = fmaf(ww, sp[11], v11);
        }
        float m = fmaxf(fmaxf(v00, v01), fmaxf(v10, v11));
        m = fmaxf(m, 0.0f);
        g_buf4[(b * 515 + g) * 25 + py * 5 + px] = m;
    }
}

// ---------------------------------------------------------------------------
// oo: 1x1 conv 515->100 over 5x5, +bias, +relu; output stored flattened
// [b, oc*25 + pix] matching reference reshape order.
// block = (b, quarter of output channels); input tile in dynamic smem.
// ---------------------------------------------------------------------------
__global__ void oo_kernel(const float* __restrict__ w,
                          const float* __restrict__ bias) {
    extern __shared__ float s[];  // 515*25 floats = 51.5 KB
    int b = blockIdx.x >> 2;
    int q = blockIdx.x & 3;
    const float* src = g_buf4 + b * 515 * 25;
    for (int i = threadIdx.x; i < 515 * 25; i += blockDim.x) s[i] = src[i];
    __syncthreads();

    for (int o = q * 625 + threadIdx.x; o < (q + 1) * 625; o += blockDim.x) {
        int oc = o / 25;
        int pix = o % 25;
        const float* wr = w + oc * 515;
        float acc = __ldg(bias + oc);
#pragma unroll 5
        for (int c = 0; c < 515; c++)
            acc = fmaf(__ldg(wr + c), s[c * 25 + pix], acc);
        g_buf5[b * 2500 + o] = fmaxf(acc, 0.0f);
    }
}

// ---------------------------------------------------------------------------
// fc1: [64,2500] x [2500,120]^T + bias, relu. Warp per output, float4 loads.
// ---------------------------------------------------------------------------
__global__ void fc1_kernel(const float* __restrict__ w,
                           const float* __restrict__ bias) {
    int wid = (blockIdx.x * blockDim.x + threadIdx.x) >> 5;
    int lane = threadIdx.x & 31;
    if (wid >= BATCH * 120) return;
    int b = wid / 120;
    int o = wid % 120;
    const float4* in = reinterpret_cast<const float4*>(g_buf5 + b * 2500);
    const float4* wr = reinterpret_cast<const float4*>(w + o * 2500);
    float acc = 0.0f;
    for (int i = lane; i < 625; i += 32) {
        float4 a = in[i];
        float4 ww = __ldg(wr + i);
        acc = fmaf(a.x, ww.x, acc);
        acc = fmaf(a.y, ww.y, acc);
        acc = fmaf(a.z, ww.z, acc);
        acc = fmaf(a.w, ww.w, acc);
    }
#pragma unroll
    for (int off = 16; off; off >>= 1)
        acc += __shfl_xor_sync(0xffffffffu, acc, off);
    if (lane == 0) g_buf6[wid] = fmaxf(acc + __ldg(bias + o), 0.0f);
}

// ---------------------------------------------------------------------------
// fc2 (relu) + fc3 fused. block per batch element.
// ---------------------------------------------------------------------------
__global__ void fc_tail_kernel(const float* __restrict__ w2,
                               const float* __restrict__ b2,
                               const float* __restrict__ w3,
                               const float* __restrict__ b3,
                               float* __restrict__ out) {
    __shared__ float h1[120];
    __shared__ float h2[84];
    int b = blockIdx.x;
    int t = threadIdx.x;
    if (t < 120) h1[t] = g_buf6[b * 120 + t];
    __syncthreads();
    if (t < 84) {
        float acc = __ldg(b2 + t);
        const float* wr = w2 + t * 120;
#pragma unroll 4
        for (int c = 0; c < 120; c++) acc = fmaf(__ldg(wr + c), h1[c], acc);
        h2[t] = fmaxf(acc, 0.0f);
    }
    __syncthreads();
    if (t < 10) {
        float acc = __ldg(b3 + t);
        const float* wr = w3 + t * 84;
#pragma unroll 4
        for (int c = 0; c < 84; c++) acc = fmaf(__ldg(wr + c), h2[c], acc);
        out[b * 10 + t] = acc;
    }
}

// ---------------------------------------------------------------------------
extern "C" void kernel_launch(void* const* d_in, const int* in_sizes, int n_in,
                              void* d_out, int out_size) {
    const float* x     = (const float*)d_in[0];
    const float* dw1_w = (const float*)d_in[1];
    const float* dw1_b = (const float*)d_in[2];
    const float* pc1_w = (const float*)d_in[3];
    const float* pc1_b = (const float*)d_in[4];
    const float* dw2_w = (const float*)d_in[5];
    const float* dw2_b = (const float*)d_in[6];
    const float* pc2_w = (const float*)d_in[7];
    const float* pc2_b = (const float*)d_in[8];
    const float* oo_w  = (const float*)d_in[9];
    const float* oo_b  = (const float*)d_in[10];
    const float* fc1_w = (const float*)d_in[11];
    const float* fc1_b = (const float*)d_in[12];
    const float* fc2_w = (const float*)d_in[13];
    const float* fc2_b = (const float*)d_in[14];
    const float* fc3_w = (const float*)d_in[15];
    const float* fc3_b = (const float*)d_in[16];
    float* out = (float*)d_out;

    // opt-in >48KB dynamic smem for oo_kernel (idempotent, not a stream op)
    static bool attr_set = false;
    if (!attr_set) {
        cudaFuncSetAttribute(oo_kernel,
                             cudaFuncAttributeMaxDynamicSharedMemorySize,
                             515 * 25 * (int)sizeof(float));
        attr_set = true;
    }

    init_groupinfo_kernel<<<3, 256>>>();

    {
        int n = BATCH * 18 * 28 * 28;
        dw1_kernel<<<(n + 255) / 256, 256>>>(x, dw1_w, dw1_b);
    }
    {
        int n = BATCH * 51 * 14 * 14;
        pc1pool_kernel<<<(n + 255) / 256, 256>>>(pc1_w, pc1_b);
    }
    {
        int n = BATCH * 255 * 100;
        dw2_kernel<<<(n + 255) / 256, 256>>>(dw2_w, dw2_b);
    }
    pc2pool_kernel<<<BATCH * 5, 256>>>(pc2_w, pc2_b);
    oo_kernel<<<BATCH * 4, 256, 515 * 25 * sizeof(float)>>>(oo_w, oo_b);
    {
        int warps = BATCH * 120;                 // one warp per output
        int threads = warps * 32;
        fc1_kernel<<<(threads + 255) / 256, 256>>>(fc1_w, fc1_b);
    }
    fc_tail_kernel<<<BATCH, 128>>>(fc2_w, fc2_b, fc3_w, fc3_b, out);
}